// round 5
// baseline (speedup 1.0000x reference)
#include <cuda_runtime.h>
#include <math.h>
#include <float.h>

#define B_DIM  256
#define T_DIM  150
#define J_DIM  25
#define FEAT   9
#define NACC   7                        // S1..S4, Vs2, Vs3, Vs4
#define SPLIT  5
#define TCHUNK (T_DIM / SPLIT)          // 30 timesteps per block
#define TPB    250                      // j = tid%25 constant per thread
#define ITEMS  (TCHUNK * J_DIM)         // 750 -> 3 items per thread
#define OUTB   (J_DIM * FEAT)           // 225
#define PARTB  (J_DIM * NACC)           // 175

__device__ float    g_scratch[B_DIM][SPLIT][PARTB];
__device__ unsigned g_ticket[B_DIM];    // zero-init; self-resetting

__device__ __forceinline__ float asqrt(float x) {
    float r;
    asm("sqrt.approx.f32 %0, %1;" : "=f"(r) : "f"(x));
    return r;
}

// sorted insert of sq into (m0<=m1<=m2<=m3), branch-free
#define INSERT4(sq, m0, m1, m2, m3) do {                  \
    float _hi;                                            \
    _hi = fmaxf(sq, m0); m0 = fminf(sq, m0); sq = _hi;    \
    _hi = fmaxf(sq, m1); m1 = fminf(sq, m1); sq = _hi;    \
    _hi = fmaxf(sq, m2); m2 = fminf(sq, m2); sq = _hi;    \
    m3 = fminf(sq, m3);                                   \
} while (0)

__global__ __launch_bounds__(TPB, 4)
void knn_feat_kernel(const float* __restrict__ x, float* __restrict__ out) {
    __shared__ float4 spos[TCHUNK][J_DIM];   // 30*25*16 = 12000 B
    __shared__ float  spart[PARTB];
    __shared__ float  sfin[PARTB];
    __shared__ bool   s_last;

    const int b   = blockIdx.x;
    const int s   = blockIdx.y;
    const int tid = threadIdx.x;

    // cooperative load of 30x25 positions; w slot = |q|^2
    const float* xb = x + ((size_t)b * T_DIM + s * TCHUNK) * (J_DIM * 3);
    for (int i = tid; i < ITEMS; i += TPB) {
        float px = xb[3 * i + 0];
        float py = xb[3 * i + 1];
        float pz = xb[3 * i + 2];
        float pp = fmaf(px, px, fmaf(py, py, pz * pz));
        spos[i / J_DIM][i % J_DIM] = make_float4(px, py, pz, pp);
    }
    for (int i = tid; i < PARTB; i += TPB) spart[i] = 0.0f;
    __syncthreads();

    const int jidx = tid % J_DIM;   // constant per thread
    const int ltb  = tid / J_DIM;   // 0..9
    const int lt0 = ltb, lt1 = ltb + 10, lt2 = ltb + 20;

    // per-chain query constants
    const float4 pA = spos[lt0][jidx];
    const float4 pB = spos[lt1][jidx];
    const float4 pC = spos[lt2][jidx];
    const float ax = -2.f * pA.x, ay = -2.f * pA.y, az = -2.f * pA.z, aw = pA.w;
    const float bx = -2.f * pB.x, by = -2.f * pB.y, bz = -2.f * pB.z, bw = pB.w;
    const float cx = -2.f * pC.x, cy = -2.f * pC.y, cz = -2.f * pC.z, cw = pC.w;

    float A0 = FLT_MAX, A1 = FLT_MAX, A2 = FLT_MAX, A3 = FLT_MAX;
    float B0 = FLT_MAX, B1 = FLT_MAX, B2 = FLT_MAX, B3 = FLT_MAX;
    float C0 = FLT_MAX, C1 = FLT_MAX, C2 = FLT_MAX, C3 = FLT_MAX;

#pragma unroll
    for (int j = 0; j < J_DIM; ++j) {
        const bool self = (j == jidx);

        float4 qa = spos[lt0][j];
        float sqa = fmaf(az, qa.z, fmaf(ay, qa.y, fmaf(ax, qa.x, aw + qa.w)));
        sqa = self ? FLT_MAX : sqa;

        float4 qb = spos[lt1][j];
        float sqb = fmaf(bz, qb.z, fmaf(by, qb.y, fmaf(bx, qb.x, bw + qb.w)));
        sqb = self ? FLT_MAX : sqb;

        float4 qc = spos[lt2][j];
        float sqc = fmaf(cz, qc.z, fmaf(cy, qc.y, fmaf(cx, qc.x, cw + qc.w)));
        sqc = self ? FLT_MAX : sqc;

        INSERT4(sqa, A0, A1, A2, A3);
        INSERT4(sqb, B0, B1, B2, B3);
        INSERT4(sqc, C0, C1, C2, C3);
    }

    float S1 = 0.f, S2 = 0.f, S3 = 0.f, S4 = 0.f;
    float V2 = 0.f, V3 = 0.f, V4 = 0.f;

#pragma unroll
    for (int c = 0; c < 3; ++c) {
        float m0, m1, m2, m3;
        if (c == 0)      { m0 = A0; m1 = A1; m2 = A2; m3 = A3; }
        else if (c == 1) { m0 = B0; m1 = B1; m2 = B2; m3 = B3; }
        else             { m0 = C0; m1 = C1; m2 = C2; m3 = C3; }

        const float d1 = asqrt(fmaxf(m0, 0.0f));
        const float d2 = asqrt(fmaxf(m1, 0.0f));
        const float d3 = asqrt(fmaxf(m2, 0.0f));
        const float d4 = asqrt(fmaxf(m3, 0.0f));

        const float s2 = fabsf(d2 - d1) * 0.70710678118654752f;
        const float a3 = (d1 + d2 + d3) * (1.0f / 3.0f);
        const float e1 = d1 - a3, e2 = d2 - a3, e3 = d3 - a3;
        const float s3 = asqrt(fmaf(e1, e1, fmaf(e2, e2, e3 * e3)) * 0.5f);
        const float a4 = (d1 + d2 + d3 + d4) * 0.25f;
        const float g1 = d1 - a4, g2 = d2 - a4, g3 = d3 - a4, g4 = d4 - a4;
        const float s4 = asqrt(fmaf(g1, g1, fmaf(g2, g2, fmaf(g3, g3, g4 * g4)))
                               * (1.0f / 3.0f));

        S1 += d1; S2 += d2; S3 += d3; S4 += d4;
        V2 += s2; V3 += s3; V4 += s4;
    }

    // combine the 10 threads sharing each j (SMEM atomics, spread addresses)
    atomicAdd(&spart[jidx * NACC + 0], S1);
    atomicAdd(&spart[jidx * NACC + 1], S2);
    atomicAdd(&spart[jidx * NACC + 2], S3);
    atomicAdd(&spart[jidx * NACC + 3], S4);
    atomicAdd(&spart[jidx * NACC + 4], V2);
    atomicAdd(&spart[jidx * NACC + 5], V3);
    atomicAdd(&spart[jidx * NACC + 6], V4);
    __syncthreads();

    // publish this split's partial
    for (int i = tid; i < PARTB; i += TPB)
        g_scratch[b][s][i] = spart[i];
    __threadfence();
    __syncthreads();

    if (tid == 0) {
        unsigned old = atomicAdd(&g_ticket[b], 1u);
        s_last = (old == SPLIT - 1);
        if (s_last) g_ticket[b] = 0;   // self-reset for next graph replay
    }
    __syncthreads();

    if (s_last) {
        __threadfence();
        for (int i = tid; i < PARTB; i += TPB) {
            float sum = 0.0f;
#pragma unroll
            for (int k = 0; k < SPLIT; ++k)
                sum += g_scratch[b][k][i];
            sfin[i] = sum;
        }
        __syncthreads();
        if (tid < OUTB) {
            const int j = tid / FEAT;
            const int f = tid % FEAT;
            const float* a = &sfin[j * NACC];
            const float t1 = a[0], t2 = a[1], t3 = a[2], t4 = a[3];
            float v;
            switch (f) {
                case 0: v = (t1 + t2) * 0.5f;               break;
                case 1: v = a[4];                           break;
                case 2: v = t1;                             break;
                case 3: v = (t1 + t2 + t3) * (1.f / 3.f);   break;
                case 4: v = a[5];                           break;
                case 5: v = t1;                             break;
                case 6: v = (t1 + t2 + t3 + t4) * 0.25f;    break;
                case 7: v = a[6];                           break;
                default: v = t1;                            break;
            }
            out[(size_t)b * OUTB + tid] = v * (1.0f / (float)T_DIM);
        }
    }
}

extern "C" void kernel_launch(void* const* d_in, const int* in_sizes, int n_in,
                              void* d_out, int out_size) {
    const float* x = (const float*)d_in[0];
    float* out = (float*)d_out;
    dim3 grid(B_DIM, SPLIT);
    knn_feat_kernel<<<grid, TPB>>>(x, out);
}

// round 6
// speedup vs baseline: 1.0820x; 1.0820x over previous
#include <cuda_runtime.h>
#include <math.h>
#include <float.h>

#define B_DIM  256
#define T_DIM  150
#define J_DIM  25
#define FEAT   9
#define NACC   7                        // S1..S4, Vs2, Vs3, Vs4
#define SPLIT  5
#define TCHUNK (T_DIM / SPLIT)          // 30 timesteps per block
#define TPB    375                      // 15*25 -> 2 items per thread
#define ITEMS  (TCHUNK * J_DIM)         // 750
#define OUTB   (J_DIM * FEAT)           // 225
#define PARTB  (J_DIM * NACC)           // 175

__device__ float    g_scratch[B_DIM][SPLIT][PARTB];
__device__ unsigned g_ticket[B_DIM];    // zero-init; self-resetting

__device__ __forceinline__ float asqrt(float x) {
    float r;
    asm("sqrt.approx.f32 %0, %1;" : "=f"(r) : "f"(x));
    return r;
}

// sorted insert of sq into (m0<=m1<=m2<=m3), branch-free
#define INSERT4(sq, m0, m1, m2, m3) do {                  \
    float _hi;                                            \
    _hi = fmaxf(sq, m0); m0 = fminf(sq, m0); sq = _hi;    \
    _hi = fmaxf(sq, m1); m1 = fminf(sq, m1); sq = _hi;    \
    _hi = fmaxf(sq, m2); m2 = fminf(sq, m2); sq = _hi;    \
    m3 = fminf(sq, m3);                                   \
} while (0)

__global__ __launch_bounds__(TPB)
void knn_feat_kernel(const float* __restrict__ x, float* __restrict__ out) {
    __shared__ float4 spos[TCHUNK][J_DIM];   // 30*25*16 = 12000 B
    __shared__ float  spart[PARTB];
    __shared__ float  sfin[PARTB];
    __shared__ bool   s_last;

    const int b   = blockIdx.x;
    const int s   = blockIdx.y;
    const int tid = threadIdx.x;

    // cooperative load of 30x25 positions; w slot = |q|^2
    const float* xb = x + ((size_t)b * T_DIM + s * TCHUNK) * (J_DIM * 3);
#pragma unroll
    for (int r = 0; r < 2; ++r) {
        int i = tid + r * TPB;
        float px = xb[3 * i + 0];
        float py = xb[3 * i + 1];
        float pz = xb[3 * i + 2];
        float pp = fmaf(px, px, fmaf(py, py, pz * pz));
        spos[i / J_DIM][i % J_DIM] = make_float4(px, py, pz, pp);
    }
    if (tid < PARTB) spart[tid] = 0.0f;
    __syncthreads();

    const int jidx = tid % J_DIM;   // constant per thread
    const int ltb  = tid / J_DIM;   // 0..14
    const int lt0 = ltb, lt1 = ltb + 15;

    // per-chain query constants
    const float4 pA = spos[lt0][jidx];
    const float4 pB = spos[lt1][jidx];
    const float ax = -2.f * pA.x, ay = -2.f * pA.y, az = -2.f * pA.z, aw = pA.w;
    const float bx = -2.f * pB.x, by = -2.f * pB.y, bz = -2.f * pB.z, bw = pB.w;

    float A0 = FLT_MAX, A1 = FLT_MAX, A2 = FLT_MAX, A3 = FLT_MAX;
    float B0 = FLT_MAX, B1 = FLT_MAX, B2 = FLT_MAX, B3 = FLT_MAX;

#pragma unroll
    for (int j = 0; j < J_DIM; ++j) {
        const bool self = (j == jidx);

        float4 qa = spos[lt0][j];   // broadcast-ish (<=2 addrs per warp)
        float sqa = fmaf(az, qa.z, fmaf(ay, qa.y, fmaf(ax, qa.x, aw + qa.w)));
        sqa = self ? FLT_MAX : sqa;

        float4 qb = spos[lt1][j];
        float sqb = fmaf(bz, qb.z, fmaf(by, qb.y, fmaf(bx, qb.x, bw + qb.w)));
        sqb = self ? FLT_MAX : sqb;

        INSERT4(sqa, A0, A1, A2, A3);
        INSERT4(sqb, B0, B1, B2, B3);
    }

    float S1 = 0.f, S2 = 0.f, S3 = 0.f, S4 = 0.f;
    float V2 = 0.f, V3 = 0.f, V4 = 0.f;

#pragma unroll
    for (int c = 0; c < 2; ++c) {
        const float m0 = (c == 0) ? A0 : B0;
        const float m1 = (c == 0) ? A1 : B1;
        const float m2 = (c == 0) ? A2 : B2;
        const float m3 = (c == 0) ? A3 : B3;

        const float d1 = asqrt(fmaxf(m0, 0.0f));
        const float d2 = asqrt(fmaxf(m1, 0.0f));
        const float d3 = asqrt(fmaxf(m2, 0.0f));
        const float d4 = asqrt(fmaxf(m3, 0.0f));

        const float s2 = fabsf(d2 - d1) * 0.70710678118654752f;
        const float a3 = (d1 + d2 + d3) * (1.0f / 3.0f);
        const float e1 = d1 - a3, e2 = d2 - a3, e3 = d3 - a3;
        const float s3 = asqrt(fmaf(e1, e1, fmaf(e2, e2, e3 * e3)) * 0.5f);
        const float a4 = (d1 + d2 + d3 + d4) * 0.25f;
        const float g1 = d1 - a4, g2 = d2 - a4, g3 = d3 - a4, g4 = d4 - a4;
        const float s4 = asqrt(fmaf(g1, g1, fmaf(g2, g2, fmaf(g3, g3, g4 * g4)))
                               * (1.0f / 3.0f));

        S1 += d1; S2 += d2; S3 += d3; S4 += d4;
        V2 += s2; V3 += s3; V4 += s4;
    }

    // combine the 15 threads sharing each j (SMEM atomics, spread addresses)
    atomicAdd(&spart[jidx * NACC + 0], S1);
    atomicAdd(&spart[jidx * NACC + 1], S2);
    atomicAdd(&spart[jidx * NACC + 2], S3);
    atomicAdd(&spart[jidx * NACC + 3], S4);
    atomicAdd(&spart[jidx * NACC + 4], V2);
    atomicAdd(&spart[jidx * NACC + 5], V3);
    atomicAdd(&spart[jidx * NACC + 6], V4);
    __syncthreads();

    // publish this split's partial
    if (tid < PARTB) g_scratch[b][s][tid] = spart[tid];
    __threadfence();
    __syncthreads();

    if (tid == 0) {
        unsigned old = atomicAdd(&g_ticket[b], 1u);
        s_last = (old == SPLIT - 1);
        if (s_last) g_ticket[b] = 0;   // self-reset for next graph replay
    }
    __syncthreads();

    if (s_last) {
        __threadfence();
        if (tid < PARTB) {
            float sum = 0.0f;
#pragma unroll
            for (int k = 0; k < SPLIT; ++k)
                sum += g_scratch[b][k][tid];
            sfin[tid] = sum;
        }
        __syncthreads();
        if (tid < OUTB) {
            const int j = tid / FEAT;
            const int f = tid % FEAT;
            const float* a = &sfin[j * NACC];
            const float t1 = a[0], t2 = a[1], t3 = a[2], t4 = a[3];
            float v;
            switch (f) {
                case 0: v = (t1 + t2) * 0.5f;               break;
                case 1: v = a[4];                           break;
                case 2: v = t1;                             break;
                case 3: v = (t1 + t2 + t3) * (1.f / 3.f);   break;
                case 4: v = a[5];                           break;
                case 5: v = t1;                             break;
                case 6: v = (t1 + t2 + t3 + t4) * 0.25f;    break;
                case 7: v = a[6];                           break;
                default: v = t1;                            break;
            }
            out[(size_t)b * OUTB + tid] = v * (1.0f / (float)T_DIM);
        }
    }
}

extern "C" void kernel_launch(void* const* d_in, const int* in_sizes, int n_in,
                              void* d_out, int out_size) {
    const float* x = (const float*)d_in[0];
    float* out = (float*)d_out;
    dim3 grid(B_DIM, SPLIT);
    knn_feat_kernel<<<grid, TPB>>>(x, out);
}